// round 11
// baseline (speedup 1.0000x reference)
#include <cuda_runtime.h>
#include <cuda_bf16.h>
#include <math_constants.h>

// Problem constants (fixed shapes for this problem)
#define NNODES 100000
#define NEDGES 1600000
#define TOTE   (NEDGES + NNODES)
#define HDIM   128
#define NG     64
#define SCAN_CHUNK 1024
#define NSCANBLK ((NNODES + SCAN_CHUNK - 1) / SCAN_CHUNK)
#define GEMM_BLOCKS ((NNODES + 127) / 128)
#define COUNT_BLOCKS ((TOTE + 255) / 256)

// ---------------- scratch (device globals; zero-initialized at load) --------
__device__ __align__(16) __nv_bfloat16 g_hb[(size_t)NNODES * HDIM]; // h in bf16
__device__ __align__(16) float g_gnn[(size_t)NNODES * HDIM];        // silu(agg+bias)
__device__ float g_as[NNODES];
__device__ float g_ad[NNODES];
__device__ int   g_deg[NNODES];
__device__ int   g_off[NNODES + 1];
__device__ int   g_cursor[NNODES];
__device__ __align__(8) int2 g_edge[TOTE];   // {src, weight-as-int}
__device__ int   g_roff[NG + 1];             // per-graph node ranges
__device__ float g_pooled[NG * HDIM];

// ---------------- helpers ----------------------------------------------------
__device__ __forceinline__ void edge_sd(const int* __restrict__ ei, int e, int E,
                                        int& s, int& d) {
    if (e < E) { s = ei[e]; d = ei[E + e]; }
    else       { s = e - E; d = s; }        // self loops appended
}

// ---------------- 1) GEMM + att epilogue, degree-count blocks fused ----------
// h is stored ONLY in bf16 (gather reads bf16; accumulation stays fp32).
__global__ __launch_bounds__(256, 2) void gemm_att_count(
    const float* __restrict__ x, const float* __restrict__ W,
    const float* __restrict__ att_src, const float* __restrict__ att_dst,
    const int* __restrict__ ei, int E, int M)
{
    if (blockIdx.x >= GEMM_BLOCKS) {
        int e = (blockIdx.x - GEMM_BLOCKS) * blockDim.x + threadIdx.x;
        if (e < E + M) {
            int s, d;
            edge_sd(ei, e, E, s, d);
            atomicAdd(&g_deg[d], 1);
        }
        return;
    }

    __shared__ __align__(16) float Xs[32][132];   // transposed: Xs[k][row]
    __shared__ __align__(16) float Ws[32][132];   // Ws[k][col]

    const int tid = threadIdx.x;
    const int tx  = tid & 15;        // col group
    const int ty  = tid >> 4;        // row group
    const int m0  = blockIdx.x * 128;

    float acc[8][8];
    #pragma unroll
    for (int r = 0; r < 8; r++)
        #pragma unroll
        for (int c = 0; c < 8; c++) acc[r][c] = 0.f;

    for (int k0 = 0; k0 < HDIM; k0 += 32) {
        #pragma unroll
        for (int i = 0; i < 4; i++) {
            int f   = tid + i * 256;           // 0..1023 float4 index
            int row = f >> 3;
            int k4  = (f & 7) * 4;
            float4 v = make_float4(0.f, 0.f, 0.f, 0.f);
            int gr = m0 + row;
            if (gr < M) v = *(const float4*)&x[(size_t)gr * HDIM + k0 + k4];
            Xs[k4 + 0][row] = v.x;
            Xs[k4 + 1][row] = v.y;
            Xs[k4 + 2][row] = v.z;
            Xs[k4 + 3][row] = v.w;
        }
        #pragma unroll
        for (int i = 0; i < 4; i++) {
            int f  = tid + i * 256;
            int kr = f >> 5;
            int c4 = (f & 31) * 4;
            *(float4*)&Ws[kr][c4] = *(const float4*)&W[(size_t)(k0 + kr) * HDIM + c4];
        }
        __syncthreads();

        #pragma unroll
        for (int kk = 0; kk < 32; kk++) {
            float a[8], b[8];
            *(float4*)&a[0] = *(const float4*)&Xs[kk][ty * 8];
            *(float4*)&a[4] = *(const float4*)&Xs[kk][ty * 8 + 4];
            *(float4*)&b[0] = *(const float4*)&Ws[kk][tx * 8];
            *(float4*)&b[4] = *(const float4*)&Ws[kk][tx * 8 + 4];
            #pragma unroll
            for (int r = 0; r < 8; r++)
                #pragma unroll
                for (int c = 0; c < 8; c++)
                    acc[r][c] += a[r] * b[c];
        }
        __syncthreads();
    }

    float asv[8], adv[8];
    #pragma unroll
    for (int c = 0; c < 8; c++) {
        asv[c] = __ldg(&att_src[tx * 8 + c]);
        adv[c] = __ldg(&att_dst[tx * 8 + c]);
    }

    #pragma unroll
    for (int r = 0; r < 8; r++) {
        int gr = m0 + ty * 8 + r;
        if (gr < M) {
            __nv_bfloat16 hb[8];
            #pragma unroll
            for (int c = 0; c < 8; c++) hb[c] = __float2bfloat16(acc[r][c]);
            *(uint4*)&g_hb[(size_t)gr * HDIM + tx * 8] = *(uint4*)hb;
        }
        float sv = 0.f, dv = 0.f;
        #pragma unroll
        for (int c = 0; c < 8; c++) {
            sv += acc[r][c] * asv[c];
            dv += acc[r][c] * adv[c];
        }
        #pragma unroll
        for (int o = 8; o; o >>= 1) {
            sv += __shfl_down_sync(0xffffffffu, sv, o, 16);
            dv += __shfl_down_sync(0xffffffffu, dv, o, 16);
        }
        if (tx == 0 && gr < M) { g_as[gr] = sv; g_ad[gr] = dv; }
    }
}

// ---------------- 2) single-kernel scan, zero inter-block communication ------
__global__ __launch_bounds__(1024) void scan_single(int n)
{
    __shared__ int wsum[32];
    __shared__ int csum[32];
    __shared__ int carry_s;
    const int tid = threadIdx.x, lane = tid & 31, w = tid >> 5;
    const int bid = blockIdx.x;

    int c = 0;
    const int limit = bid * SCAN_CHUNK;
    for (int j = tid; j < limit; j += 1024) c += g_deg[j];
    #pragma unroll
    for (int o = 16; o; o >>= 1) c += __shfl_down_sync(0xffffffffu, c, o);
    if (lane == 0) csum[w] = c;
    __syncthreads();
    if (w == 0) {
        int cc = csum[lane];
        #pragma unroll
        for (int o = 16; o; o >>= 1) cc += __shfl_down_sync(0xffffffffu, cc, o);
        if (lane == 0) carry_s = cc;
    }

    int i = bid * SCAN_CHUNK + tid;
    int v = (i < n) ? g_deg[i] : 0;
    int s = v;
    #pragma unroll
    for (int o = 1; o < 32; o <<= 1) {
        int t = __shfl_up_sync(0xffffffffu, s, o);
        if (lane >= o) s += t;
    }
    if (lane == 31) wsum[w] = s;
    __syncthreads();
    if (w == 0) {
        int ws = wsum[lane];
        #pragma unroll
        for (int o = 1; o < 32; o <<= 1) {
            int t = __shfl_up_sync(0xffffffffu, ws, o);
            if (lane >= o) ws += t;
        }
        wsum[lane] = ws;
    }
    __syncthreads();
    int prefix = (w > 0) ? wsum[w - 1] : 0;
    int excl = carry_s + prefix + s - v;
    if (i < n) { g_off[i] = excl; g_cursor[i] = excl; }
    if (bid == 0 && tid == 0) g_off[n] = TOTE;
}

// ---------------- 3) scatter edges + weights as ONE int2 store ---------------
__global__ void scatter_w(const int* __restrict__ ei, int E, int n)
{
    int e = blockIdx.x * blockDim.x + threadIdx.x;
    if (e >= E + n) return;
    int s, d;
    edge_sd(ei, e, E, s, d);
    float v = g_as[s] + g_ad[d];
    v = (v > 0.f) ? v : 0.2f * v;
    float wgt = __expf(v);               // no-max softmax: logits are small
    int pos = atomicAdd(&g_cursor[d], 1);
    g_edge[pos] = make_int2(s, __float_as_int(wgt));
}

// ---------------- 4) shuffle-free parallel gather, bf16 h (PROFILED) ---------
// warp = node; 4 edge-slots x 8 column-slots. Each lane loads 16B = 8 bf16
// per half-row; 2 half-row iterations cover HDIM=128.
__global__ __launch_bounds__(256) void node_gather(
    const float* __restrict__ bias, int n)
{
    int warp = (blockIdx.x * blockDim.x + threadIdx.x) >> 5;
    int lane = threadIdx.x & 31;
    if (warp >= n) return;

    const int s0 = g_off[warp];
    const int s1 = g_off[warp + 1];
    const int eslot = lane >> 3;     // 0..3: which edge of the group
    const int cslot = lane & 7;      // 0..7: which 16B chunk of the half-row

    float acc[2][8];
    #pragma unroll
    for (int q = 0; q < 2; q++)
        #pragma unroll
        for (int j = 0; j < 8; j++) acc[q][j] = 0.f;
    float den_l = 0.f;

    for (int base = s0; base < s1; base += 4) {
        int i = base + eslot;
        int src;
        float wt;
        if (i < s1) {
            int2 ed = __ldg(&g_edge[i]);
            src = ed.x;
            wt  = __int_as_float(ed.y);
        } else {
            src = warp;              // valid row, zero weight
            wt  = 0.f;
        }
        den_l += wt;
        const uint4* row = (const uint4*)&g_hb[(size_t)src * HDIM];
        #pragma unroll
        for (int q = 0; q < 2; q++) {
            uint4 pv = __ldg(&row[q * 8 + cslot]);   // 8 bf16 = 16B
            float2 f0 = __bfloat1622float2(*(__nv_bfloat162*)&pv.x);
            float2 f1 = __bfloat1622float2(*(__nv_bfloat162*)&pv.y);
            float2 f2 = __bfloat1622float2(*(__nv_bfloat162*)&pv.z);
            float2 f3 = __bfloat1622float2(*(__nv_bfloat162*)&pv.w);
            acc[q][0] += wt * f0.x; acc[q][1] += wt * f0.y;
            acc[q][2] += wt * f1.x; acc[q][3] += wt * f1.y;
            acc[q][4] += wt * f2.x; acc[q][5] += wt * f2.y;
            acc[q][6] += wt * f3.x; acc[q][7] += wt * f3.y;
        }
    }

    // each edge's weight was accumulated by 8 lanes -> den = warp_sum / 8
    float den = den_l;
    #pragma unroll
    for (int o = 16; o; o >>= 1) den += __shfl_xor_sync(0xffffffffu, den, o);
    den *= 0.125f;
    const float inv = 1.0f / den;    // self-loop guarantees den > 0

    // reduce accumulators across the 4 edge-slots (lane bits 3 and 4)
    #pragma unroll
    for (int q = 0; q < 2; q++)
        #pragma unroll
        for (int j = 0; j < 8; j++) {
            acc[q][j] += __shfl_xor_sync(0xffffffffu, acc[q][j], 8);
            acc[q][j] += __shfl_xor_sync(0xffffffffu, acc[q][j], 16);
        }

    if (lane < 8) {
        #pragma unroll
        for (int q = 0; q < 2; q++) {
            int cbase = q * 64 + lane * 8;
            float4 o0, o1;
            float* op = &o0.x;
            #pragma unroll
            for (int j = 0; j < 8; j++) {
                float xv = acc[q][j] * inv + __ldg(&bias[cbase + j]);
                float gv = xv / (1.f + __expf(-xv));
                if (j < 4) (&o0.x)[j] = gv; else (&o1.x)[j - 4] = gv;
            }
            (void)op;
            *(float4*)&g_gnn[(size_t)warp * HDIM + cbase]     = o0;
            *(float4*)&g_gnn[(size_t)warp * HDIM + cbase + 4] = o1;
        }
    }
}

// ---------------- 5) graph ranges (batch is sorted) --------------------------
__global__ void graph_ranges(const int* __restrict__ batch, int n)
{
    int i = blockIdx.x * blockDim.x + threadIdx.x;
    if (i >= n) return;
    int b = batch[i];
    if (i == 0) {
        for (int g = 0; g <= b; g++) g_roff[g] = 0;
    } else {
        int pb = batch[i - 1];
        for (int g = pb + 1; g <= b; g++) g_roff[g] = i;
    }
    if (i == n - 1) {
        for (int g = b + 1; g <= NG; g++) g_roff[g] = n;
    }
}

// ---------------- 6) pool: branch-free streaming per (graph, col-tile) -------
__global__ __launch_bounds__(128) void pool2(int n)
{
    const int g    = blockIdx.x;
    const int col  = blockIdx.y * 32 + (threadIdx.x & 31);
    const int trow = threadIdx.x >> 5;    // 0..3
    const int r0 = g_roff[g];
    const int r1 = g_roff[g + 1];

    float a0 = 0.f, a1 = 0.f, a2 = 0.f, a3 = 0.f;
    int r = r0 + trow;
    for (; r + 12 < r1; r += 16) {
        a0 += g_gnn[(size_t)(r)      * HDIM + col];
        a1 += g_gnn[(size_t)(r + 4)  * HDIM + col];
        a2 += g_gnn[(size_t)(r + 8)  * HDIM + col];
        a3 += g_gnn[(size_t)(r + 12) * HDIM + col];
    }
    for (; r < r1; r += 4) a0 += g_gnn[(size_t)r * HDIM + col];
    float acc = (a0 + a1) + (a2 + a3);

    __shared__ float sm[128];
    sm[threadIdx.x] = acc;
    __syncthreads();
    if (trow == 0) {
        int c = threadIdx.x;   // 0..31
        float s = sm[c] + sm[32 + c] + sm[64 + c] + sm[96 + c];
        g_pooled[g * HDIM + col] = s;
    }
}

// ---------------- 7) final head (count from ranges) --------------------------
__global__ void final_kernel(const float* __restrict__ fin_w,
                             const float* __restrict__ fin_b,
                             float* __restrict__ out)
{
    int gidx = blockIdx.x;
    int t = threadIdx.x;             // 128 threads
    __shared__ float red[4];
    float cnt = (float)(g_roff[gidx + 1] - g_roff[gidx]);
    float inv = 1.f / fmaxf(cnt, 1.f);
    float p = g_pooled[gidx * HDIM + t] * inv * fin_w[t];
    #pragma unroll
    for (int o = 16; o; o >>= 1) p += __shfl_down_sync(0xffffffffu, p, o);
    if ((t & 31) == 0) red[t >> 5] = p;
    __syncthreads();
    if (t == 0) out[gidx] = red[0] + red[1] + red[2] + red[3] + fin_b[0];
}

// ---------------- 8) tail: re-zero g_deg for the next launch/replay ----------
__global__ void tail_zero(int n)
{
    int i = blockIdx.x * blockDim.x + threadIdx.x;
    if (i < n) g_deg[i] = 0;
}

// ---------------- launch ------------------------------------------------------
// ncu captures the 4th kernel launch -> node_gather stays profiled.
extern "C" void kernel_launch(void* const* d_in, const int* in_sizes, int n_in,
                              void* d_out, int out_size)
{
    const float* x       = (const float*)d_in[0];
    const int*   ei      = (const int*)  d_in[1];
    const int*   batch   = (const int*)  d_in[2];
    const float* W       = (const float*)d_in[3];
    const float* att_src = (const float*)d_in[4];
    const float* att_dst = (const float*)d_in[5];
    const float* bias    = (const float*)d_in[6];
    const float* fin_w   = (const float*)d_in[7];
    const float* fin_b   = (const float*)d_in[8];
    float* out = (float*)d_out;

    const int n   = in_sizes[0] / HDIM;   // 100000
    const int E   = in_sizes[1] / 2;      // 1600000
    const int tot = E + n;

    // 1: GEMM + attention logits, degree counting fused into extra blocks
    gemm_att_count<<<GEMM_BLOCKS + COUNT_BLOCKS, 256>>>(x, W, att_src, att_dst,
                                                        ei, E, n);
    // 2: exclusive scan (communication-free single kernel)
    scan_single<<<NSCANBLK, 1024>>>(n);
    // 3: scatter + precompute softmax weights (one int2 store per edge)
    int eblocks = (tot + 255) / 256;
    scatter_w<<<eblocks, 256>>>(ei, E, n);
    // 4: aggregation + silu, bf16 h stream (PROFILED)
    int wblocks = (n * 32 + 255) / 256;
    node_gather<<<wblocks, 256>>>(bias, n);
    // 5: per-graph node ranges
    graph_ranges<<<(n + 255) / 256, 256>>>(batch, n);
    // 6: streaming mean-pool (sum; divide in final)
    pool2<<<dim3(NG, 4), 128>>>(n);
    // 7: head
    final_kernel<<<NG, 128>>>(fin_w, fin_b, out);
    // 8: re-zero degree histogram for the next launch / graph replay
    tail_zero<<<(n + 255) / 256, 256>>>(n);
}

// round 13
// speedup vs baseline: 1.4624x; 1.4624x over previous
#include <cuda_runtime.h>
#include <cuda_bf16.h>
#include <math_constants.h>

// Problem constants (fixed shapes for this problem)
#define NNODES 100000
#define NEDGES 1600000
#define TOTE   (NEDGES + NNODES)
#define HDIM   128
#define NG     64
#define SCAN_CHUNK 1024
#define NSCANBLK ((NNODES + SCAN_CHUNK - 1) / SCAN_CHUNK)
#define GEMM_BLOCKS ((NNODES + 127) / 128)
#define CNT_PER_BLK 1024
#define CNT_BLOCKS ((TOTE + CNT_PER_BLK - 1) / CNT_PER_BLK)
#define XS_STRIDE 136           // bf16 elements per row (8-pad: conflict-free ldmatrix)
#define DSMEM_BYTES (2 * 128 * XS_STRIDE * 2)   // Xs + Ws, bf16

// ---------------- scratch (device globals; zero-initialized at load) --------
__device__ __align__(16) float g_h[(size_t)NNODES * HDIM];     // x @ W (fp32 out)
__device__ __align__(16) float g_gnn[(size_t)NNODES * HDIM];   // silu(agg+bias)
__device__ float g_as[NNODES];
__device__ float g_ad[NNODES];
__device__ int   g_deg[NNODES];
__device__ int   g_off[NNODES + 1];
__device__ int   g_cursor[NNODES];
__device__ int   g_esrc[TOTE];
__device__ float g_ew[TOTE];
__device__ int   g_roff[NG + 1];
__device__ float g_pooled[NG * HDIM];

// ---------------- helpers ------------------------------------------------------
__device__ __forceinline__ void edge_sd(const int* __restrict__ ei, int e, int E,
                                        int& s, int& d) {
    if (e < E) { s = ei[e]; d = ei[E + e]; }
    else       { s = e - E; d = s; }        // self loops appended
}
__device__ __forceinline__ unsigned smem_u32(const void* p) {
    unsigned a;
    asm("{ .reg .u64 t; cvta.to.shared.u64 t, %1; cvt.u32.u64 %0, t; }"
        : "=r"(a) : "l"(p));
    return a;
}
#define LDMATRIX_X4(r0, r1, r2, r3, addr)                                      \
    asm volatile("ldmatrix.sync.aligned.m8n8.x4.shared.b16 {%0,%1,%2,%3}, [%4];" \
        : "=r"(r0), "=r"(r1), "=r"(r2), "=r"(r3) : "r"(addr))
#define LDMATRIX_X4_T(r0, r1, r2, r3, addr)                                    \
    asm volatile("ldmatrix.sync.aligned.m8n8.x4.trans.shared.b16 {%0,%1,%2,%3}, [%4];" \
        : "=r"(r0), "=r"(r1), "=r"(r2), "=r"(r3) : "r"(addr))
#define MMA_BF16(d0, d1, d2, d3, a0, a1, a2, a3, b0, b1)                       \
    asm volatile("mma.sync.aligned.m16n8k16.row.col.f32.bf16.bf16.f32 "        \
        "{%0,%1,%2,%3}, {%4,%5,%6,%7}, {%8,%9}, {%0,%1,%2,%3};"                \
        : "+f"(d0), "+f"(d1), "+f"(d2), "+f"(d3)                               \
        : "r"(a0), "r"(a1), "r"(a2), "r"(a3), "r"(b0), "r"(b1))

// ---------------- 1) HMMA GEMM h = x@W + att epilogue, count fused -----------
// 256 threads = 8 warps; warp w owns rows [w*16, w*16+16) of the 128-row tile,
// full N=128. bf16 operands staged in dynamic smem, fp32 accumulate.
__global__ __launch_bounds__(256) void gemm_mma_count(
    const float* __restrict__ x, const float* __restrict__ W,
    const float* __restrict__ att_src, const float* __restrict__ att_dst,
    const int* __restrict__ ei, int E, int M)
{
    if (blockIdx.x >= GEMM_BLOCKS) {
        int base = (blockIdx.x - GEMM_BLOCKS) * CNT_PER_BLK + threadIdx.x;
        #pragma unroll
        for (int j = 0; j < 4; j++) {
            int e = base + j * 256;
            if (e < E + M) {
                int s, d;
                edge_sd(ei, e, E, s, d);
                atomicAdd(&g_deg[d], 1);
            }
        }
        return;
    }

    extern __shared__ __align__(16) unsigned char dsmem[];
    __nv_bfloat16* Xs = (__nv_bfloat16*)dsmem;                    // [128][136]
    __nv_bfloat16* Ws = Xs + 128 * XS_STRIDE;                     // [128][136]
    __shared__ float s_av[128], s_dv[128];

    const int tid  = threadIdx.x;
    const int wid  = tid >> 5;
    const int lane = tid & 31;
    const int m0   = blockIdx.x * 128;

    // stage X tile (rows m0..m0+127) and full W as bf16
    #pragma unroll
    for (int i = 0; i < 16; i++) {
        int f   = tid + i * 256;            // float4 index 0..4095
        int row = f >> 5;
        int c4  = (f & 31) * 4;
        int gr  = m0 + row;
        float4 v = (gr < M) ? __ldg((const float4*)&x[(size_t)gr * HDIM + c4])
                            : make_float4(0.f, 0.f, 0.f, 0.f);
        __nv_bfloat162 p0 = __floats2bfloat162_rn(v.x, v.y);
        __nv_bfloat162 p1 = __floats2bfloat162_rn(v.z, v.w);
        *(__nv_bfloat162*)&Xs[row * XS_STRIDE + c4]     = p0;
        *(__nv_bfloat162*)&Xs[row * XS_STRIDE + c4 + 2] = p1;

        float4 wv = __ldg((const float4*)&W[(size_t)row * HDIM + c4]);
        __nv_bfloat162 q0 = __floats2bfloat162_rn(wv.x, wv.y);
        __nv_bfloat162 q1 = __floats2bfloat162_rn(wv.z, wv.w);
        *(__nv_bfloat162*)&Ws[row * XS_STRIDE + c4]     = q0;
        *(__nv_bfloat162*)&Ws[row * XS_STRIDE + c4 + 2] = q1;
    }
    if (tid < 128) { s_av[tid] = __ldg(&att_src[tid]); s_dv[tid] = __ldg(&att_dst[tid]); }
    __syncthreads();

    const unsigned xs_base = smem_u32(Xs);
    const unsigned ws_base = smem_u32(Ws);
    // per-lane ldmatrix address offsets (bf16 elements)
    const unsigned a_off = (unsigned)((wid * 16 + (lane & 15)) * XS_STRIDE
                                      + (lane >> 4) * 8);
    const unsigned b_off = (unsigned)((lane & 15) * XS_STRIDE + (lane >> 4) * 8);

    float acc[16][4];
    #pragma unroll
    for (int nt = 0; nt < 16; nt++)
        #pragma unroll
        for (int j = 0; j < 4; j++) acc[nt][j] = 0.f;

    #pragma unroll
    for (int ks = 0; ks < 8; ks++) {
        const int k0 = ks * 16;
        unsigned a0, a1, a2, a3;
        LDMATRIX_X4(a0, a1, a2, a3, xs_base + (a_off + k0) * 2);
        #pragma unroll
        for (int np = 0; np < 8; np++) {
            unsigned b0, b1, b2, b3;
            LDMATRIX_X4_T(b0, b1, b2, b3,
                          ws_base + (b_off + k0 * XS_STRIDE + np * 16) * 2);
            MMA_BF16(acc[np * 2][0], acc[np * 2][1], acc[np * 2][2], acc[np * 2][3],
                     a0, a1, a2, a3, b0, b1);
            MMA_BF16(acc[np * 2 + 1][0], acc[np * 2 + 1][1],
                     acc[np * 2 + 1][2], acc[np * 2 + 1][3],
                     a0, a1, a2, a3, b2, b3);
        }
    }

    // epilogue: store h rows + fused attention dots
    const int q  = lane & 3;          // col pair within n-tile
    const int r0 = m0 + wid * 16 + (lane >> 2);
    const int r1 = r0 + 8;
    float sv0 = 0.f, dv0 = 0.f, sv1 = 0.f, dv1 = 0.f;
    #pragma unroll
    for (int nt = 0; nt < 16; nt++) {
        int c = nt * 8 + q * 2;
        float av0 = s_av[c], av1 = s_av[c + 1];
        float bv0 = s_dv[c], bv1 = s_dv[c + 1];
        sv0 += acc[nt][0] * av0 + acc[nt][1] * av1;
        dv0 += acc[nt][0] * bv0 + acc[nt][1] * bv1;
        sv1 += acc[nt][2] * av0 + acc[nt][3] * av1;
        dv1 += acc[nt][2] * bv0 + acc[nt][3] * bv1;
        if (r0 < M)
            *(float2*)&g_h[(size_t)r0 * HDIM + c] = make_float2(acc[nt][0], acc[nt][1]);
        if (r1 < M)
            *(float2*)&g_h[(size_t)r1 * HDIM + c] = make_float2(acc[nt][2], acc[nt][3]);
    }
    // reduce across the 4 lanes of each quad (same r0/r1)
    #pragma unroll
    for (int o = 1; o < 4; o <<= 1) {
        sv0 += __shfl_xor_sync(0xffffffffu, sv0, o);
        dv0 += __shfl_xor_sync(0xffffffffu, dv0, o);
        sv1 += __shfl_xor_sync(0xffffffffu, sv1, o);
        dv1 += __shfl_xor_sync(0xffffffffu, dv1, o);
    }
    if (q == 0) {
        if (r0 < M) { g_as[r0] = sv0; g_ad[r0] = dv0; }
        if (r1 < M) { g_as[r1] = sv1; g_ad[r1] = dv1; }
    }
}

// ---------------- 2) single-kernel scan, zero inter-block communication ------
__global__ __launch_bounds__(1024) void scan_single(int n)
{
    __shared__ int wsum[32];
    __shared__ int csum[32];
    __shared__ int carry_s;
    const int tid = threadIdx.x, lane = tid & 31, w = tid >> 5;
    const int bid = blockIdx.x;

    int c = 0;
    const int limit = bid * SCAN_CHUNK;
    for (int j = tid; j < limit; j += 1024) c += g_deg[j];
    #pragma unroll
    for (int o = 16; o; o >>= 1) c += __shfl_down_sync(0xffffffffu, c, o);
    if (lane == 0) csum[w] = c;
    __syncthreads();
    if (w == 0) {
        int cc = csum[lane];
        #pragma unroll
        for (int o = 16; o; o >>= 1) cc += __shfl_down_sync(0xffffffffu, cc, o);
        if (lane == 0) carry_s = cc;
    }

    int i = bid * SCAN_CHUNK + tid;
    int v = (i < n) ? g_deg[i] : 0;
    int s = v;
    #pragma unroll
    for (int o = 1; o < 32; o <<= 1) {
        int t = __shfl_up_sync(0xffffffffu, s, o);
        if (lane >= o) s += t;
    }
    if (lane == 31) wsum[w] = s;
    __syncthreads();
    if (w == 0) {
        int ws = wsum[lane];
        #pragma unroll
        for (int o = 1; o < 32; o <<= 1) {
            int t = __shfl_up_sync(0xffffffffu, ws, o);
            if (lane >= o) ws += t;
        }
        wsum[lane] = ws;
    }
    __syncthreads();
    int prefix = (w > 0) ? wsum[w - 1] : 0;
    int excl = carry_s + prefix + s - v;
    if (i < n) { g_off[i] = excl; g_cursor[i] = excl; }
    if (bid == 0 && tid == 0) g_off[n] = TOTE;
}

// ---------------- 3) scatter edges + precompute softmax weights --------------
__global__ void scatter_w(const int* __restrict__ ei, int E, int n)
{
    int e = blockIdx.x * blockDim.x + threadIdx.x;
    if (e >= E + n) return;
    int s, d;
    edge_sd(ei, e, E, s, d);
    float v = g_as[s] + g_ad[d];
    v = (v > 0.f) ? v : 0.2f * v;
    float wgt = __expf(v);               // no-max softmax: logits are small
    int pos = atomicAdd(&g_cursor[d], 1);
    g_esrc[pos] = s;
    g_ew[pos]   = wgt;
}

// ---------------- 4) shuffle-free parallel gather (R10-exact) -----------------
__global__ __launch_bounds__(256) void node_gather(
    const float* __restrict__ bias, int n)
{
    int warp = (blockIdx.x * blockDim.x + threadIdx.x) >> 5;
    int lane = threadIdx.x & 31;
    if (warp >= n) return;

    const int s0 = g_off[warp];
    const int s1 = g_off[warp + 1];
    const int eslot = lane >> 3;     // 0..3: which edge of the group
    const int cslot = lane & 7;      // 0..7: which 16B of the column quarter

    float4 acc[4];
    #pragma unroll
    for (int q = 0; q < 4; q++) acc[q] = make_float4(0.f, 0.f, 0.f, 0.f);
    float den_l = 0.f;

    for (int base = s0; base < s1; base += 4) {
        int i = base + eslot;
        int src;
        float wt;
        if (i < s1) {
            src = __ldg(&g_esrc[i]);
            wt  = __ldg(&g_ew[i]);
        } else {
            src = warp;              // valid row, zero weight
            wt  = 0.f;
        }
        den_l += wt;
        const float* row = &g_h[(size_t)src * HDIM + cslot * 4];
        #pragma unroll
        for (int q = 0; q < 4; q++) {
            float4 hv = *(const float4*)&row[q * 32];
            acc[q].x += wt * hv.x;
            acc[q].y += wt * hv.y;
            acc[q].z += wt * hv.z;
            acc[q].w += wt * hv.w;
        }
    }

    float den = den_l;
    #pragma unroll
    for (int o = 16; o; o >>= 1) den += __shfl_xor_sync(0xffffffffu, den, o);
    den *= 0.125f;
    const float inv = 1.0f / den;    // self-loop guarantees den > 0

    #pragma unroll
    for (int q = 0; q < 4; q++) {
        acc[q].x += __shfl_xor_sync(0xffffffffu, acc[q].x, 8);
        acc[q].y += __shfl_xor_sync(0xffffffffu, acc[q].y, 8);
        acc[q].z += __shfl_xor_sync(0xffffffffu, acc[q].z, 8);
        acc[q].w += __shfl_xor_sync(0xffffffffu, acc[q].w, 8);
        acc[q].x += __shfl_xor_sync(0xffffffffu, acc[q].x, 16);
        acc[q].y += __shfl_xor_sync(0xffffffffu, acc[q].y, 16);
        acc[q].z += __shfl_xor_sync(0xffffffffu, acc[q].z, 16);
        acc[q].w += __shfl_xor_sync(0xffffffffu, acc[q].w, 16);
    }

    if (lane < 8) {
        const float4* bias4 = (const float4*)bias;
        #pragma unroll
        for (int q = 0; q < 4; q++) {
            float4 b4 = __ldg(&bias4[q * 8 + lane]);
            float x0 = acc[q].x * inv + b4.x;
            float x1 = acc[q].y * inv + b4.y;
            float x2 = acc[q].z * inv + b4.z;
            float x3 = acc[q].w * inv + b4.w;
            float4 g;
            g.x = x0 / (1.f + __expf(-x0));
            g.y = x1 / (1.f + __expf(-x1));
            g.z = x2 / (1.f + __expf(-x2));
            g.w = x3 / (1.f + __expf(-x3));
            *(float4*)&g_gnn[(size_t)warp * HDIM + q * 32 + lane * 4] = g;
        }
    }
}

// ---------------- 5) graph ranges (batch is sorted) --------------------------
__global__ void graph_ranges(const int* __restrict__ batch, int n)
{
    int i = blockIdx.x * blockDim.x + threadIdx.x;
    if (i >= n) return;
    int b = batch[i];
    if (i == 0) {
        for (int g = 0; g <= b; g++) g_roff[g] = 0;
    } else {
        int pb = batch[i - 1];
        for (int g = pb + 1; g <= b; g++) g_roff[g] = i;
    }
    if (i == n - 1) {
        for (int g = b + 1; g <= NG; g++) g_roff[g] = n;
    }
}

// ---------------- 6) pool: branch-free streaming per (graph, col-tile) -------
__global__ __launch_bounds__(128) void pool2(int n)
{
    const int g    = blockIdx.x;
    const int col  = blockIdx.y * 32 + (threadIdx.x & 31);
    const int trow = threadIdx.x >> 5;    // 0..3
    const int r0 = g_roff[g];
    const int r1 = g_roff[g + 1];

    float a0 = 0.f, a1 = 0.f, a2 = 0.f, a3 = 0.f;
    int r = r0 + trow;
    for (; r + 12 < r1; r += 16) {
        a0 += g_gnn[(size_t)(r)      * HDIM + col];
        a1 += g_gnn[(size_t)(r + 4)  * HDIM + col];
        a2 += g_gnn[(size_t)(r + 8)  * HDIM + col];
        a3 += g_gnn[(size_t)(r + 12) * HDIM + col];
    }
    for (; r < r1; r += 4) a0 += g_gnn[(size_t)r * HDIM + col];
    float acc = (a0 + a1) + (a2 + a3);

    __shared__ float sm[128];
    sm[threadIdx.x] = acc;
    __syncthreads();
    if (trow == 0) {
        int c = threadIdx.x;   // 0..31
        float s = sm[c] + sm[32 + c] + sm[64 + c] + sm[96 + c];
        g_pooled[g * HDIM + col] = s;
    }
}

// ---------------- 7) final head (count from ranges) --------------------------
__global__ void final_kernel(const float* __restrict__ fin_w,
                             const float* __restrict__ fin_b,
                             float* __restrict__ out)
{
    int gidx = blockIdx.x;
    int t = threadIdx.x;             // 128 threads
    __shared__ float red[4];
    float cnt = (float)(g_roff[gidx + 1] - g_roff[gidx]);
    float inv = 1.f / fmaxf(cnt, 1.f);
    float p = g_pooled[gidx * HDIM + t] * inv * fin_w[t];
    #pragma unroll
    for (int o = 16; o; o >>= 1) p += __shfl_down_sync(0xffffffffu, p, o);
    if ((t & 31) == 0) red[t >> 5] = p;
    __syncthreads();
    if (t == 0) out[gidx] = red[0] + red[1] + red[2] + red[3] + fin_b[0];
}

// ---------------- 8) tail: re-zero g_deg for the next launch/replay ----------
__global__ void tail_zero(int n)
{
    int i = blockIdx.x * blockDim.x + threadIdx.x;
    if (i < n) g_deg[i] = 0;
}

// ---------------- launch ------------------------------------------------------
// ncu captures the 4th kernel launch -> node_gather stays profiled.
extern "C" void kernel_launch(void* const* d_in, const int* in_sizes, int n_in,
                              void* d_out, int out_size)
{
    const float* x       = (const float*)d_in[0];
    const int*   ei      = (const int*)  d_in[1];
    const int*   batch   = (const int*)  d_in[2];
    const float* W       = (const float*)d_in[3];
    const float* att_src = (const float*)d_in[4];
    const float* att_dst = (const float*)d_in[5];
    const float* bias    = (const float*)d_in[6];
    const float* fin_w   = (const float*)d_in[7];
    const float* fin_b   = (const float*)d_in[8];
    float* out = (float*)d_out;

    const int n   = in_sizes[0] / HDIM;   // 100000
    const int E   = in_sizes[1] / 2;      // 1600000
    const int tot = E + n;

    static int smem_set = 0;
    if (!smem_set) {
        cudaFuncSetAttribute(gemm_mma_count,
                             cudaFuncAttributeMaxDynamicSharedMemorySize,
                             DSMEM_BYTES);
        smem_set = 1;
    }

    // 1: HMMA GEMM + attention logits, degree counting fused as tail blocks
    gemm_mma_count<<<GEMM_BLOCKS + CNT_BLOCKS, 256, DSMEM_BYTES>>>(
        x, W, att_src, att_dst, ei, E, n);
    // 2: exclusive scan (communication-free single kernel)
    scan_single<<<NSCANBLK, 1024>>>(n);
    // 3: scatter + precompute softmax weights
    int eblocks = (tot + 255) / 256;
    scatter_w<<<eblocks, 256>>>(ei, E, n);
    // 4: aggregation + silu (PROFILED)
    int wblocks = (n * 32 + 255) / 256;
    node_gather<<<wblocks, 256>>>(bias, n);
    // 5: per-graph node ranges
    graph_ranges<<<(n + 255) / 256, 256>>>(batch, n);
    // 6: streaming mean-pool (sum; divide in final)
    pool2<<<dim3(NG, 4), 128>>>(n);
    // 7: head
    final_kernel<<<NG, 128>>>(fin_w, fin_b, out);
    // 8: re-zero degree histogram for the next launch / graph replay
    tail_zero<<<(n + 255) / 256, 256>>>(n);
}

// round 14
// speedup vs baseline: 1.5895x; 1.0869x over previous
#include <cuda_runtime.h>
#include <cuda_bf16.h>
#include <math_constants.h>

// Problem constants (fixed shapes for this problem)
#define NNODES 100000
#define NEDGES 1600000
#define TOTE   (NEDGES + NNODES)
#define HDIM   128
#define NG     64
#define SCAN_CHUNK 1024
#define NSCANBLK ((NNODES + SCAN_CHUNK - 1) / SCAN_CHUNK)
#define GEMM_BLOCKS ((NNODES + 127) / 128)
#define CNT_PER_BLK 1024
#define CNT_BLOCKS ((TOTE + CNT_PER_BLK - 1) / CNT_PER_BLK)
#define RZ_BLOCKS ((NNODES + 255) / 256)
#define XS_STRIDE 136           // bf16 elements per row (8-pad: conflict-free ldmatrix)
#define DSMEM_BYTES (2 * 128 * XS_STRIDE * 2)   // Xs + Ws, bf16

// ---------------- scratch (device globals; zero-initialized at load) --------
// g_deg is re-zeroed by the scatter launch's tail blocks every call.
__device__ __align__(16) float g_h[(size_t)NNODES * HDIM];     // x @ W (fp32 out)
__device__ __align__(16) float g_gnn[(size_t)NNODES * HDIM];   // silu(agg+bias)
__device__ float g_as[NNODES];
__device__ float g_ad[NNODES];
__device__ int   g_deg[NNODES];
__device__ int   g_off[NNODES + 1];
__device__ int   g_cursor[NNODES];
__device__ __align__(8) int2 g_edge[TOTE];   // {src, weight-as-int-bits}
__device__ int   g_roff[NG + 1];
__device__ float g_pooled[NG * HDIM];

// ---------------- helpers ------------------------------------------------------
__device__ __forceinline__ void edge_sd(const int* __restrict__ ei, int e, int E,
                                        int& s, int& d) {
    if (e < E) { s = ei[e]; d = ei[E + e]; }
    else       { s = e - E; d = s; }        // self loops appended
}
__device__ __forceinline__ unsigned smem_u32(const void* p) {
    unsigned a;
    asm("{ .reg .u64 t; cvta.to.shared.u64 t, %1; cvt.u32.u64 %0, t; }"
        : "=r"(a) : "l"(p));
    return a;
}
#define LDMATRIX_X4(r0, r1, r2, r3, addr)                                      \
    asm volatile("ldmatrix.sync.aligned.m8n8.x4.shared.b16 {%0,%1,%2,%3}, [%4];" \
        : "=r"(r0), "=r"(r1), "=r"(r2), "=r"(r3) : "r"(addr))
#define LDMATRIX_X4_T(r0, r1, r2, r3, addr)                                    \
    asm volatile("ldmatrix.sync.aligned.m8n8.x4.trans.shared.b16 {%0,%1,%2,%3}, [%4];" \
        : "=r"(r0), "=r"(r1), "=r"(r2), "=r"(r3) : "r"(addr))
#define MMA_BF16(d0, d1, d2, d3, a0, a1, a2, a3, b0, b1)                       \
    asm volatile("mma.sync.aligned.m16n8k16.row.col.f32.bf16.bf16.f32 "        \
        "{%0,%1,%2,%3}, {%4,%5,%6,%7}, {%8,%9}, {%0,%1,%2,%3};"                \
        : "+f"(d0), "+f"(d1), "+f"(d2), "+f"(d3)                               \
        : "r"(a0), "r"(a1), "r"(a2), "r"(a3), "r"(b0), "r"(b1))

// ---------------- 1) HMMA GEMM h = x@W + att epilogue, count fused -----------
__global__ __launch_bounds__(256) void gemm_mma_count(
    const float* __restrict__ x, const float* __restrict__ W,
    const float* __restrict__ att_src, const float* __restrict__ att_dst,
    const int* __restrict__ ei, int E, int M)
{
    if (blockIdx.x >= GEMM_BLOCKS) {
        // degree count: 4 consecutive edges per thread, int4 dst loads
        int e0 = (blockIdx.x - GEMM_BLOCKS) * CNT_PER_BLK + threadIdx.x * 4;
        if (e0 + 3 < E) {
            int4 d4 = *(const int4*)&ei[E + e0];
            atomicAdd(&g_deg[d4.x], 1);
            atomicAdd(&g_deg[d4.y], 1);
            atomicAdd(&g_deg[d4.z], 1);
            atomicAdd(&g_deg[d4.w], 1);
        } else {
            #pragma unroll
            for (int j = 0; j < 4; j++) {
                int e = e0 + j;
                if (e < E + M) {
                    int d = (e < E) ? ei[E + e] : (e - E);
                    atomicAdd(&g_deg[d], 1);
                }
            }
        }
        return;
    }

    extern __shared__ __align__(16) unsigned char dsmem[];
    __nv_bfloat16* Xs = (__nv_bfloat16*)dsmem;                    // [128][136]
    __nv_bfloat16* Ws = Xs + 128 * XS_STRIDE;                     // [128][136]
    __shared__ float s_av[128], s_dv[128];

    const int tid  = threadIdx.x;
    const int wid  = tid >> 5;
    const int lane = tid & 31;
    const int m0   = blockIdx.x * 128;

    #pragma unroll
    for (int i = 0; i < 16; i++) {
        int f   = tid + i * 256;            // float4 index 0..4095
        int row = f >> 5;
        int c4  = (f & 31) * 4;
        int gr  = m0 + row;
        float4 v = (gr < M) ? __ldg((const float4*)&x[(size_t)gr * HDIM + c4])
                            : make_float4(0.f, 0.f, 0.f, 0.f);
        __nv_bfloat162 p0 = __floats2bfloat162_rn(v.x, v.y);
        __nv_bfloat162 p1 = __floats2bfloat162_rn(v.z, v.w);
        *(__nv_bfloat162*)&Xs[row * XS_STRIDE + c4]     = p0;
        *(__nv_bfloat162*)&Xs[row * XS_STRIDE + c4 + 2] = p1;

        float4 wv = __ldg((const float4*)&W[(size_t)row * HDIM + c4]);
        __nv_bfloat162 q0 = __floats2bfloat162_rn(wv.x, wv.y);
        __nv_bfloat162 q1 = __floats2bfloat162_rn(wv.z, wv.w);
        *(__nv_bfloat162*)&Ws[row * XS_STRIDE + c4]     = q0;
        *(__nv_bfloat162*)&Ws[row * XS_STRIDE + c4 + 2] = q1;
    }
    if (tid < 128) { s_av[tid] = __ldg(&att_src[tid]); s_dv[tid] = __ldg(&att_dst[tid]); }
    __syncthreads();

    const unsigned xs_base = smem_u32(Xs);
    const unsigned ws_base = smem_u32(Ws);
    const unsigned a_off = (unsigned)((wid * 16 + (lane & 15)) * XS_STRIDE
                                      + (lane >> 4) * 8);
    const unsigned b_off = (unsigned)((lane & 15) * XS_STRIDE + (lane >> 4) * 8);

    float acc[16][4];
    #pragma unroll
    for (int nt = 0; nt < 16; nt++)
        #pragma unroll
        for (int j = 0; j < 4; j++) acc[nt][j] = 0.f;

    #pragma unroll
    for (int ks = 0; ks < 8; ks++) {
        const int k0 = ks * 16;
        unsigned a0, a1, a2, a3;
        LDMATRIX_X4(a0, a1, a2, a3, xs_base + (a_off + k0) * 2);
        #pragma unroll
        for (int np = 0; np < 8; np++) {
            unsigned b0, b1, b2, b3;
            LDMATRIX_X4_T(b0, b1, b2, b3,
                          ws_base + (b_off + k0 * XS_STRIDE + np * 16) * 2);
            MMA_BF16(acc[np * 2][0], acc[np * 2][1], acc[np * 2][2], acc[np * 2][3],
                     a0, a1, a2, a3, b0, b1);
            MMA_BF16(acc[np * 2 + 1][0], acc[np * 2 + 1][1],
                     acc[np * 2 + 1][2], acc[np * 2 + 1][3],
                     a0, a1, a2, a3, b2, b3);
        }
    }

    const int q  = lane & 3;
    const int r0 = m0 + wid * 16 + (lane >> 2);
    const int r1 = r0 + 8;
    float sv0 = 0.f, dv0 = 0.f, sv1 = 0.f, dv1 = 0.f;
    #pragma unroll
    for (int nt = 0; nt < 16; nt++) {
        int c = nt * 8 + q * 2;
        float av0 = s_av[c], av1 = s_av[c + 1];
        float bv0 = s_dv[c], bv1 = s_dv[c + 1];
        sv0 += acc[nt][0] * av0 + acc[nt][1] * av1;
        dv0 += acc[nt][0] * bv0 + acc[nt][1] * bv1;
        sv1 += acc[nt][2] * av0 + acc[nt][3] * av1;
        dv1 += acc[nt][2] * bv0 + acc[nt][3] * bv1;
        if (r0 < M)
            *(float2*)&g_h[(size_t)r0 * HDIM + c] = make_float2(acc[nt][0], acc[nt][1]);
        if (r1 < M)
            *(float2*)&g_h[(size_t)r1 * HDIM + c] = make_float2(acc[nt][2], acc[nt][3]);
    }
    #pragma unroll
    for (int o = 1; o < 4; o <<= 1) {
        sv0 += __shfl_xor_sync(0xffffffffu, sv0, o);
        dv0 += __shfl_xor_sync(0xffffffffu, dv0, o);
        sv1 += __shfl_xor_sync(0xffffffffu, sv1, o);
        dv1 += __shfl_xor_sync(0xffffffffu, dv1, o);
    }
    if (q == 0) {
        if (r0 < M) { g_as[r0] = sv0; g_ad[r0] = dv0; }
        if (r1 < M) { g_as[r1] = sv1; g_ad[r1] = dv1; }
    }
}

// ---------------- 2) single-kernel scan, zero inter-block communication ------
__global__ __launch_bounds__(1024) void scan_single(int n)
{
    __shared__ int wsum[32];
    __shared__ int csum[32];
    __shared__ int carry_s;
    const int tid = threadIdx.x, lane = tid & 31, w = tid >> 5;
    const int bid = blockIdx.x;

    int c = 0;
    const int limit = bid * SCAN_CHUNK;
    for (int j = tid; j < limit; j += 1024) c += g_deg[j];
    #pragma unroll
    for (int o = 16; o; o >>= 1) c += __shfl_down_sync(0xffffffffu, c, o);
    if (lane == 0) csum[w] = c;
    __syncthreads();
    if (w == 0) {
        int cc = csum[lane];
        #pragma unroll
        for (int o = 16; o; o >>= 1) cc += __shfl_down_sync(0xffffffffu, cc, o);
        if (lane == 0) carry_s = cc;
    }

    int i = bid * SCAN_CHUNK + tid;
    int v = (i < n) ? g_deg[i] : 0;
    int s = v;
    #pragma unroll
    for (int o = 1; o < 32; o <<= 1) {
        int t = __shfl_up_sync(0xffffffffu, s, o);
        if (lane >= o) s += t;
    }
    if (lane == 31) wsum[w] = s;
    __syncthreads();
    if (w == 0) {
        int ws = wsum[lane];
        #pragma unroll
        for (int o = 1; o < 32; o <<= 1) {
            int t = __shfl_up_sync(0xffffffffu, ws, o);
            if (lane >= o) ws += t;
        }
        wsum[lane] = ws;
    }
    __syncthreads();
    int prefix = (w > 0) ? wsum[w - 1] : 0;
    int excl = carry_s + prefix + s - v;
    if (i < n) { g_off[i] = excl; g_cursor[i] = excl; }
    if (bid == 0 && tid == 0) g_off[n] = TOTE;
}

// ---------------- 3) scatter (int2 pack) + fused ranges + g_deg re-zero ------
// Tail blocks (>= eblocks): graph ranges (batch sorted) + zero g_deg for the
// next replay (legal: scan already consumed g_deg in the previous launch).
__global__ void scatter_w(const int* __restrict__ ei,
                          const int* __restrict__ batch,
                          int E, int n, int eblocks)
{
    if (blockIdx.x >= eblocks) {
        int i = (blockIdx.x - eblocks) * blockDim.x + threadIdx.x;
        if (i < n) {
            g_deg[i] = 0;
            int b = batch[i];
            if (i == 0) {
                for (int g = 0; g <= b; g++) g_roff[g] = 0;
            } else {
                int pb = batch[i - 1];
                for (int g = pb + 1; g <= b; g++) g_roff[g] = i;
            }
            if (i == n - 1) {
                for (int g = b + 1; g <= NG; g++) g_roff[g] = n;
            }
        }
        return;
    }
    int e = blockIdx.x * blockDim.x + threadIdx.x;
    if (e >= E + n) return;
    int s, d;
    edge_sd(ei, e, E, s, d);
    float v = g_as[s] + g_ad[d];
    v = (v > 0.f) ? v : 0.2f * v;
    float wgt = __expf(v);               // no-max softmax: logits are small
    int pos = atomicAdd(&g_cursor[d], 1);
    g_edge[pos] = make_int2(s, __float_as_int(wgt));
}

// ---------------- 4) shuffle-free parallel gather (PROFILED) ------------------
__global__ __launch_bounds__(256) void node_gather(
    const float* __restrict__ bias, int n)
{
    int warp = (blockIdx.x * blockDim.x + threadIdx.x) >> 5;
    int lane = threadIdx.x & 31;
    if (warp >= n) return;

    const int s0 = g_off[warp];
    const int s1 = g_off[warp + 1];
    const int eslot = lane >> 3;     // 0..3: which edge of the group
    const int cslot = lane & 7;      // 0..7: which 16B of the column quarter

    float4 acc[4];
    #pragma unroll
    for (int q = 0; q < 4; q++) acc[q] = make_float4(0.f, 0.f, 0.f, 0.f);
    float den_l = 0.f;

    for (int base = s0; base < s1; base += 4) {
        int i = base + eslot;
        int src;
        float wt;
        if (i < s1) {
            int2 ed = __ldg(&g_edge[i]);
            src = ed.x;
            wt  = __int_as_float(ed.y);
        } else {
            src = warp;              // valid row, zero weight
            wt  = 0.f;
        }
        den_l += wt;
        const float* row = &g_h[(size_t)src * HDIM + cslot * 4];
        #pragma unroll
        for (int q = 0; q < 4; q++) {
            float4 hv = *(const float4*)&row[q * 32];
            acc[q].x += wt * hv.x;
            acc[q].y += wt * hv.y;
            acc[q].z += wt * hv.z;
            acc[q].w += wt * hv.w;
        }
    }

    float den = den_l;
    #pragma unroll
    for (int o = 16; o; o >>= 1) den += __shfl_xor_sync(0xffffffffu, den, o);
    den *= 0.125f;
    const float inv = 1.0f / den;    // self-loop guarantees den > 0

    #pragma unroll
    for (int q = 0; q < 4; q++) {
        acc[q].x += __shfl_xor_sync(0xffffffffu, acc[q].x, 8);
        acc[q].y += __shfl_xor_sync(0xffffffffu, acc[q].y, 8);
        acc[q].z += __shfl_xor_sync(0xffffffffu, acc[q].z, 8);
        acc[q].w += __shfl_xor_sync(0xffffffffu, acc[q].w, 8);
        acc[q].x += __shfl_xor_sync(0xffffffffu, acc[q].x, 16);
        acc[q].y += __shfl_xor_sync(0xffffffffu, acc[q].y, 16);
        acc[q].z += __shfl_xor_sync(0xffffffffu, acc[q].z, 16);
        acc[q].w += __shfl_xor_sync(0xffffffffu, acc[q].w, 16);
    }

    if (lane < 8) {
        const float4* bias4 = (const float4*)bias;
        #pragma unroll
        for (int q = 0; q < 4; q++) {
            float4 b4 = __ldg(&bias4[q * 8 + lane]);
            float x0 = acc[q].x * inv + b4.x;
            float x1 = acc[q].y * inv + b4.y;
            float x2 = acc[q].z * inv + b4.z;
            float x3 = acc[q].w * inv + b4.w;
            float4 g;
            g.x = x0 / (1.f + __expf(-x0));
            g.y = x1 / (1.f + __expf(-x1));
            g.z = x2 / (1.f + __expf(-x2));
            g.w = x3 / (1.f + __expf(-x3));
            *(float4*)&g_gnn[(size_t)warp * HDIM + q * 32 + lane * 4] = g;
        }
    }
}

// ---------------- 5) pool: branch-free streaming per (graph, col-tile) -------
__global__ __launch_bounds__(128) void pool2(int n)
{
    const int g    = blockIdx.x;
    const int col  = blockIdx.y * 32 + (threadIdx.x & 31);
    const int trow = threadIdx.x >> 5;    // 0..3
    const int r0 = g_roff[g];
    const int r1 = g_roff[g + 1];

    float a0 = 0.f, a1 = 0.f, a2 = 0.f, a3 = 0.f;
    int r = r0 + trow;
    for (; r + 12 < r1; r += 16) {
        a0 += g_gnn[(size_t)(r)      * HDIM + col];
        a1 += g_gnn[(size_t)(r + 4)  * HDIM + col];
        a2 += g_gnn[(size_t)(r + 8)  * HDIM + col];
        a3 += g_gnn[(size_t)(r + 12) * HDIM + col];
    }
    for (; r < r1; r += 4) a0 += g_gnn[(size_t)r * HDIM + col];
    float acc = (a0 + a1) + (a2 + a3);

    __shared__ float sm[128];
    sm[threadIdx.x] = acc;
    __syncthreads();
    if (trow == 0) {
        int c = threadIdx.x;   // 0..31
        float s = sm[c] + sm[32 + c] + sm[64 + c] + sm[96 + c];
        g_pooled[g * HDIM + col] = s;
    }
}

// ---------------- 6) final head (count from ranges) --------------------------
__global__ void final_kernel(const float* __restrict__ fin_w,
                             const float* __restrict__ fin_b,
                             float* __restrict__ out)
{
    int gidx = blockIdx.x;
    int t = threadIdx.x;             // 128 threads
    __shared__ float red[4];
    float cnt = (float)(g_roff[gidx + 1] - g_roff[gidx]);
    float inv = 1.f / fmaxf(cnt, 1.f);
    float p = g_pooled[gidx * HDIM + t] * inv * fin_w[t];
    #pragma unroll
    for (int o = 16; o; o >>= 1) p += __shfl_down_sync(0xffffffffu, p, o);
    if ((t & 31) == 0) red[t >> 5] = p;
    __syncthreads();
    if (t == 0) out[gidx] = red[0] + red[1] + red[2] + red[3] + fin_b[0];
}

// ---------------- launch ------------------------------------------------------
// ncu captures the 4th kernel launch -> node_gather stays profiled.
extern "C" void kernel_launch(void* const* d_in, const int* in_sizes, int n_in,
                              void* d_out, int out_size)
{
    const float* x       = (const float*)d_in[0];
    const int*   ei      = (const int*)  d_in[1];
    const int*   batch   = (const int*)  d_in[2];
    const float* W       = (const float*)d_in[3];
    const float* att_src = (const float*)d_in[4];
    const float* att_dst = (const float*)d_in[5];
    const float* bias    = (const float*)d_in[6];
    const float* fin_w   = (const float*)d_in[7];
    const float* fin_b   = (const float*)d_in[8];
    float* out = (float*)d_out;

    const int n   = in_sizes[0] / HDIM;   // 100000
    const int E   = in_sizes[1] / 2;      // 1600000
    const int tot = E + n;

    static int smem_set = 0;
    if (!smem_set) {
        cudaFuncSetAttribute(gemm_mma_count,
                             cudaFuncAttributeMaxDynamicSharedMemorySize,
                             DSMEM_BYTES);
        smem_set = 1;
    }

    // 1: HMMA GEMM + attention logits, degree counting fused as tail blocks
    gemm_mma_count<<<GEMM_BLOCKS + CNT_BLOCKS, 256, DSMEM_BYTES>>>(
        x, W, att_src, att_dst, ei, E, n);
    // 2: exclusive scan (communication-free single kernel)
    scan_single<<<NSCANBLK, 1024>>>(n);
    // 3: scatter (int2 pack) + fused graph-ranges + g_deg re-zero tail blocks
    int eblocks = (tot + 255) / 256;
    scatter_w<<<eblocks + RZ_BLOCKS, 256>>>(ei, batch, E, n, eblocks);
    // 4: aggregation + silu (PROFILED)
    int wblocks = (n * 32 + 255) / 256;
    node_gather<<<wblocks, 256>>>(bias, n);
    // 5: streaming mean-pool (sum; divide in final)
    pool2<<<dim3(NG, 4), 128>>>(n);
    // 6: head
    final_kernel<<<NG, 128>>>(fin_w, fin_b, out);
}